// round 14
// baseline (speedup 1.0000x reference)
#include <cuda_runtime.h>
#include <cuda_bf16.h>
#include <math.h>
#include <stdint.h>

// ---------------- problem constants ----------------
#define N_MAX 40000
#define E_MAX 640000
#define F_IN  512
#define H     128
#define C_OUT 40
#define NEG_SLOPE 0.01f

// ---------------- scratch (device globals; no runtime alloc) ----------------
__device__ float g_xh [N_MAX * H];
__device__ float g_t  [N_MAX * H];

__device__ __nv_bfloat16 g_xh_h[N_MAX * H];
__device__ __nv_bfloat16 g_xh_l[N_MAX * H];
__device__ __nv_bfloat16 g_tx_h[N_MAX * H];
__device__ __nv_bfloat16 g_tx_l[N_MAX * H];
__device__ __nv_bfloat16 g_s_h [N_MAX * H];
__device__ __nv_bfloat16 g_s_l [N_MAX * H];
__device__ __nv_bfloat16 g_t_h [N_MAX * H];
__device__ __nv_bfloat16 g_t_l [N_MAX * H];

__device__ float g_deg   [N_MAX];
__device__ float g_dis   [N_MAX];
__device__ float g_loopw [N_MAX];
__device__ float g_invcnt[N_MAX];
__device__ int   g_nloop [N_MAX];
__device__ int   g_hist  [N_MAX];
__device__ int   g_off   [N_MAX + 1];
__device__ int   g_cursor[N_MAX];
__device__ int   g_bsum  [64];
__device__ int   g_esrc  [E_MAX];
__device__ float g_enorm [E_MAX];
__device__ float g_ewe   [E_MAX];

__device__ float g_W12[H * H];
__device__ float g_b12[H];
__device__ float g_Wc [H * C_OUT];
__device__ float g_bc [C_OUT];

// B in mma-fragment order: hi plane [K*64 u32] then lo plane [K*64 u32].
__device__ uint32_t g_Fpre1 [2 * 512 * 64];
__device__ uint32_t g_Fcw0_1[2 * 128 * 64];
__device__ uint32_t g_Fcw1_1[2 * 128 * 64];
__device__ uint32_t g_Fsw1  [2 * 128 * 64];
__device__ uint32_t g_FW12  [2 * 128 * 64];
__device__ uint32_t g_Fcw0_2[2 * 128 * 64];
__device__ uint32_t g_Fcw1_2[2 * 128 * 64];
__device__ uint32_t g_Fsw2  [2 * 128 * 64];

// ---------------- helpers ----------------
__device__ __forceinline__ uint32_t smem_u32(const void* p) {
    uint32_t a;
    asm("{ .reg .u64 t; cvta.to.shared.u64 t, %1; cvt.u32.u64 %0, t; }"
        : "=r"(a) : "l"(p));
    return a;
}
__device__ __forceinline__ void split2(float a, float b, uint32_t& h, uint32_t& l) {
    asm("cvt.rn.bf16x2.f32 %0,%1,%2;" : "=r"(h) : "f"(b), "f"(a));
    float fa = __uint_as_float(h << 16);
    float fb = __uint_as_float(h & 0xFFFF0000u);
    float la = a - fa, lb = b - fb;
    asm("cvt.rn.bf16x2.f32 %0,%1,%2;" : "=r"(l) : "f"(lb), "f"(la));
}
__device__ __forceinline__ void ldm4(uint32_t* r, uint32_t addr) {
    asm volatile("ldmatrix.sync.aligned.m8n8.x4.shared.b16 {%0,%1,%2,%3},[%4];"
                 : "=r"(r[0]), "=r"(r[1]), "=r"(r[2]), "=r"(r[3]) : "r"(addr));
}
__device__ __forceinline__ void mma16816(float* d, const uint32_t* a, uint32_t b0, uint32_t b1) {
    asm volatile("mma.sync.aligned.m16n8k16.row.col.f32.bf16.bf16.f32 "
                 "{%0,%1,%2,%3},{%4,%5,%6,%7},{%8,%9},{%0,%1,%2,%3};"
                 : "+f"(d[0]), "+f"(d[1]), "+f"(d[2]), "+f"(d[3])
                 : "r"(a[0]), "r"(a[1]), "r"(a[2]), "r"(a[3]), "r"(b0), "r"(b1));
}
__device__ __forceinline__ void cp16(uint32_t dst, const void* src, int szbytes) {
    asm volatile("cp.async.cg.shared.global [%0],[%1],16,%2;"
                 :: "r"(dst), "l"(src), "r"(szbytes));
}
template<int NN> __device__ __forceinline__ void cp_wait() {
    asm volatile("cp.async.wait_group %0;" :: "n"(NN));
}

// ---------------- preprocessing kernels ----------------
__global__ void init_nodes(float* loopw, float* deg, int* nloop, int* hist, int n) {
    int i = blockIdx.x * blockDim.x + threadIdx.x;
    if (i < n) { loopw[i] = 1.0f; deg[i] = 0.0f; nloop[i] = 0; hist[i] = 0; }
}

__global__ void edge_pass1(const int* __restrict__ src, const int* __restrict__ dst,
                           const float* __restrict__ w,
                           float* __restrict__ deg, int* __restrict__ nloop,
                           float* __restrict__ loopw, int* __restrict__ hist, int E) {
    int i = blockIdx.x * blockDim.x + threadIdx.x;
    if (i >= E) return;
    int s = src[i], d = dst[i];
    float wt = w[i];
    if (s == d) {
        loopw[s] = wt;
        atomicAdd(&nloop[s], 1);
    } else {
        atomicAdd(&deg[s], wt);
    }
    atomicAdd(&hist[d], 1);
}

__global__ void scan1(const int* __restrict__ hist, int* __restrict__ bsum,
                      const float* __restrict__ deg, const int* __restrict__ nloop,
                      float* __restrict__ dis, float* __restrict__ invcnt, int n) {
    __shared__ int sh[256];
    int base = blockIdx.x * 1024;
    int s = 0;
#pragma unroll
    for (int j = 0; j < 4; j++) {
        int i = base + threadIdx.x + j * 256;
        if (i < n) {
            int h = hist[i];
            s += h;
            float dg = deg[i];
            dis[i]    = (dg > 0.0f) ? rsqrtf(dg) : 0.0f;
            invcnt[i] = 1.0f / ((float)(h - nloop[i]) + 1.0f);
        }
    }
    sh[threadIdx.x] = s;
    __syncthreads();
    for (int o = 128; o > 0; o >>= 1) {
        if (threadIdx.x < o) sh[threadIdx.x] += sh[threadIdx.x + o];
        __syncthreads();
    }
    if (threadIdx.x == 0) bsum[blockIdx.x] = sh[0];
}
__global__ void scan2(int* __restrict__ bsum, int nb, int* __restrict__ off, int n) {
    if (threadIdx.x == 0) {
        int run = 0;
        for (int i = 0; i < nb; i++) { int v = bsum[i]; bsum[i] = run; run += v; }
        off[n] = run;
    }
}
__global__ void scan3(const int* __restrict__ hist, const int* __restrict__ bsum,
                      int* __restrict__ off, int* __restrict__ cursor, int n) {
    __shared__ int sh[256];
    int base = blockIdx.x * 1024 + threadIdx.x * 4;
    int v[4]; int s = 0;
#pragma unroll
    for (int j = 0; j < 4; j++) {
        int i = base + j;
        v[j] = (i < n) ? hist[i] : 0;
        s += v[j];
    }
    sh[threadIdx.x] = s;
    __syncthreads();
    for (int o = 1; o < 256; o <<= 1) {
        int t = (threadIdx.x >= o) ? sh[threadIdx.x - o] : 0;
        __syncthreads();
        sh[threadIdx.x] += t;
        __syncthreads();
    }
    int run = bsum[blockIdx.x] + sh[threadIdx.x] - s;
#pragma unroll
    for (int j = 0; j < 4; j++) {
        int i = base + j;
        if (i < n) { off[i] = run; cursor[i] = run; }
        run += v[j];
    }
}

__global__ void edge_pass2(const int* __restrict__ src, const int* __restrict__ dst,
                           const float* __restrict__ w, const float* __restrict__ dis,
                           int* __restrict__ cursor,
                           int* __restrict__ esrc, float* __restrict__ enorm,
                           float* __restrict__ ewe, int E) {
    int i = blockIdx.x * blockDim.x + threadIdx.x;
    if (i >= E) return;
    int s = src[i], d = dst[i];
    float wt = w[i];
    float wc = (s == d) ? 0.0f : wt;
    float nm = -dis[s] * wc * dis[d];
    int pos = atomicAdd(&cursor[d], 1);
    esrc[pos]  = s;
    enorm[pos] = nm;
    ewe[pos]   = wc;
}

// warp-per-node CSR aggregation with fused sage-mean; emits bf16 hi/lo planes
__global__ void __launch_bounds__(256) aggregate(
        const float* __restrict__ xh, const int* __restrict__ off,
        const int* __restrict__ esrc, const float* __restrict__ enorm,
        const float* __restrict__ ewe,
        const float* __restrict__ loopw, const float* __restrict__ invcnt,
        __nv_bfloat16* __restrict__ txh, __nv_bfloat16* __restrict__ txl,
        __nv_bfloat16* __restrict__ sh,  __nv_bfloat16* __restrict__ sl, int N) {
    int warp = (blockIdx.x * blockDim.x + threadIdx.x) >> 5;
    int lane = threadIdx.x & 31;
    if (warp >= N) return;
    int beg = off[warp], end = off[warp + 1];
    const float4* xh4 = (const float4*)xh;
    float4 a1 = make_float4(0, 0, 0, 0);
    float4 a2 = make_float4(0, 0, 0, 0);
    int j = beg;
    for (; j + 4 <= end; j += 4) {
        int   s0 = __ldg(&esrc[j]),     s1 = __ldg(&esrc[j + 1]);
        int   s2 = __ldg(&esrc[j + 2]), s3 = __ldg(&esrc[j + 3]);
        float n0 = __ldg(&enorm[j]),     n1 = __ldg(&enorm[j + 1]);
        float n2 = __ldg(&enorm[j + 2]), n3 = __ldg(&enorm[j + 3]);
        float w0 = __ldg(&ewe[j]),       w1 = __ldg(&ewe[j + 1]);
        float w2 = __ldg(&ewe[j + 2]),   w3 = __ldg(&ewe[j + 3]);
        float4 v0 = __ldg(&xh4[(size_t)s0 * 32 + lane]);
        float4 v1 = __ldg(&xh4[(size_t)s1 * 32 + lane]);
        float4 v2 = __ldg(&xh4[(size_t)s2 * 32 + lane]);
        float4 v3 = __ldg(&xh4[(size_t)s3 * 32 + lane]);
        a1.x += n0 * v0.x + n1 * v1.x + n2 * v2.x + n3 * v3.x;
        a1.y += n0 * v0.y + n1 * v1.y + n2 * v2.y + n3 * v3.y;
        a1.z += n0 * v0.z + n1 * v1.z + n2 * v2.z + n3 * v3.z;
        a1.w += n0 * v0.w + n1 * v1.w + n2 * v2.w + n3 * v3.w;
        a2.x += w0 * v0.x + w1 * v1.x + w2 * v2.x + w3 * v3.x;
        a2.y += w0 * v0.y + w1 * v1.y + w2 * v2.y + w3 * v3.y;
        a2.z += w0 * v0.z + w1 * v1.z + w2 * v2.z + w3 * v3.z;
        a2.w += w0 * v0.w + w1 * v1.w + w2 * v2.w + w3 * v3.w;
    }
    for (; j < end; j++) {
        int sn = __ldg(&esrc[j]);
        float nm = __ldg(&enorm[j]);
        float we = __ldg(&ewe[j]);
        float4 v = __ldg(&xh4[(size_t)sn * 32 + lane]);
        a1.x += nm * v.x; a1.y += nm * v.y; a1.z += nm * v.z; a1.w += nm * v.w;
        a2.x += we * v.x; a2.y += we * v.y; a2.z += we * v.z; a2.w += we * v.w;
    }
    float lw = __ldg(&loopw[warp]);
    float ic = __ldg(&invcnt[warp]);
    float4 xv = __ldg(&xh4[(size_t)warp * 32 + lane]);
    a2.x = (a2.x + lw * xv.x) * ic;
    a2.y = (a2.y + lw * xv.y) * ic;
    a2.z = (a2.z + lw * xv.z) * ic;
    a2.w = (a2.w + lw * xv.w) * ic;
    uint32_t h0, l0, h1, l1;
    int idx = warp * 32 + lane;
    split2(a1.x, a1.y, h0, l0);
    split2(a1.z, a1.w, h1, l1);
    ((uint2*)txh)[idx] = make_uint2(h0, h1);
    ((uint2*)txl)[idx] = make_uint2(l0, l1);
    split2(a2.x, a2.y, h0, l0);
    split2(a2.z, a2.w, h1, l1);
    ((uint2*)sh)[idx] = make_uint2(h0, h1);
    ((uint2*)sl)[idx] = make_uint2(l0, l1);
}

// ---------------- setup kernels ----------------
__device__ __forceinline__ void wfuse_body(
        const float* __restrict__ A, const float* __restrict__ B,
        const float* __restrict__ bA, const float* __restrict__ bB,
        float* __restrict__ W, float* __restrict__ bOut, int K2, int blk) {
    int c = threadIdx.x;
    if (c >= K2) return;
    if (blk < H) {
        float acc = 0.0f;
        for (int j = 0; j < H; j++) acc += __ldg(&A[blk * H + j]) * __ldg(&B[j * K2 + c]);
        W[blk * K2 + c] = acc;
    } else {
        float acc = bB[c];
        for (int j = 0; j < H; j++) acc += __ldg(&bA[j]) * __ldg(&B[j * K2 + c]);
        bOut[c] = acc;
    }
}

// prestage W[K][128] -> fragment-order hi/lo u32 planes
__device__ __forceinline__ void prestage_frag(const float* __restrict__ W,
                                              uint32_t* __restrict__ out,
                                              int K, int tid, int nthreads) {
    int total = K * 64;
    for (int i = tid; i < total; i += nthreads) {
        int sub = i & 3, jo = sub >> 1, r = sub & 1;
        int q = i >> 2;
        int lane = q & 31;
        int t = q >> 5;
        int jp = t & 7, ks = t >> 3;
        int k = ks * 16 + (lane & 3) * 2 + r * 8;
        int n = (jp * 2 + jo) * 8 + (lane >> 2);
        float v0 = __ldg(&W[(size_t)k * 128 + n]);
        float v1 = __ldg(&W[(size_t)(k + 1) * 128 + n]);
        uint32_t h, l;
        split2(v0, v1, h, l);
        out[i] = h;
        out[total + i] = l;
    }
}

__global__ void setup1(
        const float* lw1, const float* pw2, const float* lb1, const float* pb2,
        const float* lw2, const float* clsw, const float* lb2, const float* clsb,
        const float* pw1,
        float* W12, float* b12, float* Wc, float* bc, uint32_t* Fpre1) {
    int b = blockIdx.x;
    if (b < 129) {
        wfuse_body(lw1, pw2, lb1, pb2, W12, b12, H, b);
    } else if (b < 258) {
        wfuse_body(lw2, clsw, lb2, clsb, Wc, bc, C_OUT, b - 129);
    } else {
        prestage_frag(pw1, Fpre1, 512, (b - 258) * 256 + threadIdx.x, 64 * 256);
    }
}

__global__ void prestage_all(
        const float* W0, const float* W1, const float* W2, const float* W3,
        const float* W4, const float* W5, const float* W6,
        uint32_t* O0, uint32_t* O1, uint32_t* O2, uint32_t* O3,
        uint32_t* O4, uint32_t* O5, uint32_t* O6) {
    int wsel = blockIdx.x >> 4;
    int bi = blockIdx.x & 15;
    const float* W; uint32_t* O;
    switch (wsel) {
        case 0: W = W0; O = O0; break;
        case 1: W = W1; O = O1; break;
        case 2: W = W2; O = O2; break;
        case 3: W = W3; O = O3; break;
        case 4: W = W4; O = O4; break;
        case 5: W = W5; O = O5; break;
        default: W = W6; O = O6; break;
    }
    prestage_frag(W, O, 128, bi * 256 + threadIdx.x, 16 * 256);
}

// ---------------- shared GEMM-pipeline core (K=128 per stream) -------------
#define TG_STRIDE 40
#define ARR_B 10240
#define STAGE_B 20480
#define TG_SMEM (2 * STAGE_B)   // 40960

__device__ __forceinline__ void pipeline_gemm(
        uint32_t base, uint32_t s_a, int growc, int asz, int K,
        const __nv_bfloat16* Ah0, const __nv_bfloat16* Al0,
        const __nv_bfloat16* Ah1, const __nv_bfloat16* Al1,
        const uint32_t* F0, const uint32_t* F1, int nstream,
        int warp_n, int lane, int a_off, float (&acc)[2][8][4]) {
    int K64 = K * 64;
    int r_half = s_a;  // already byte offset
    int cpa = K >> 5;
    int total = cpa * nstream;

    auto issue = [&](int c, int stage) {
        int st = (c >= cpa) ? 1 : 0;
        int ci = c - (st ? cpa : 0);
        const __nv_bfloat16* Ah = st ? Ah1 : Ah0;
        const __nv_bfloat16* Al = st ? Al1 : Al0;
        int k0 = ci << 5;
        uint32_t sb = base + stage * STAGE_B + r_half;
        // recover row/half from byte offset: r_half = r*80 + half*32
        // but we just need global addresses; caller passed growc & half-based ptr math:
        (void)sb;
        // computed below
    };
    (void)issue;

    // NOTE: address math inlined directly (issue lambda needs r/half; recompute here)
    int tid = threadIdx.x;
    int r = tid >> 1, half = tid & 1;

    auto issue2 = [&](int c, int stage) {
        int st = (c >= cpa) ? 1 : 0;
        int ci = c - (st ? cpa : 0);
        const __nv_bfloat16* Ah = st ? Ah1 : Ah0;
        const __nv_bfloat16* Al = st ? Al1 : Al0;
        int k0 = ci << 5;
        uint32_t sb = base + stage * STAGE_B + s_a;
        const char* gah = (const char*)(Ah + (size_t)growc * K + k0 + half * 16);
        const char* gal = (const char*)(Al + (size_t)growc * K + k0 + half * 16);
        cp16(sb,              gah,      asz);
        cp16(sb + 16,         gah + 16, asz);
        cp16(sb + ARR_B,      gal,      asz);
        cp16(sb + ARR_B + 16, gal + 16, asz);
        asm volatile("cp.async.commit_group;");
    };
    (void)r;

    issue2(0, 0);
    for (int c = 0; c < total; c++) {
        int cur = c & 1;
        int st = (c >= cpa) ? 1 : 0;
        int ci = c - (st ? cpa : 0);
        const uint32_t* Fb = st ? F1 : F0;
        const uint4* F4h = (const uint4*)Fb;
        const uint4* F4l = (const uint4*)(Fb + K64);
        cp_wait<0>();
        __syncthreads();
        if (c + 1 < total) issue2(c + 1, cur ^ 1);

        uint32_t uAh = base + cur * STAGE_B;
        uint32_t uAl = uAh + ARR_B;
#pragma unroll
        for (int ks = 0; ks < 2; ks++) {
            int ko = ks * 32;
            int kidx = ci * 2 + ks;
            int qb = (kidx * 8 + warp_n * 4) * 32 + lane;
            uint4 fh[4], fl[4];
#pragma unroll
            for (int nj = 0; nj < 4; nj++) fh[nj] = __ldg(&F4h[qb + nj * 32]);
#pragma unroll
            for (int nj = 0; nj < 4; nj++) fl[nj] = __ldg(&F4l[qb + nj * 32]);
            uint32_t afh[2][4], afl[2][4];
#pragma unroll
            for (int mi = 0; mi < 2; mi++) {
                ldm4(afh[mi], uAh + a_off + ko + mi * 16 * TG_STRIDE * 2);
                ldm4(afl[mi], uAl + a_off + ko + mi * 16 * TG_STRIDE * 2);
            }
#pragma unroll
            for (int mi = 0; mi < 2; mi++)
#pragma unroll
                for (int ni = 0; ni < 8; ni++) {
                    uint32_t b0 = (ni & 1) ? fh[ni >> 1].z : fh[ni >> 1].x;
                    uint32_t b1 = (ni & 1) ? fh[ni >> 1].w : fh[ni >> 1].y;
                    mma16816(acc[mi][ni], afh[mi], b0, b1);
                }
#pragma unroll
            for (int mi = 0; mi < 2; mi++)
#pragma unroll
                for (int ni = 0; ni < 8; ni++) {
                    uint32_t b0 = (ni & 1) ? fh[ni >> 1].z : fh[ni >> 1].x;
                    uint32_t b1 = (ni & 1) ? fh[ni >> 1].w : fh[ni >> 1].y;
                    mma16816(acc[mi][ni], afl[mi], b0, b1);
                }
#pragma unroll
            for (int mi = 0; mi < 2; mi++)
#pragma unroll
                for (int ni = 0; ni < 8; ni++) {
                    uint32_t b0 = (ni & 1) ? fl[ni >> 1].z : fl[ni >> 1].x;
                    uint32_t b1 = (ni & 1) ? fl[ni >> 1].w : fl[ni >> 1].y;
                    mma16816(acc[mi][ni], afh[mi], b0, b1);
                }
        }
    }
}

// ---------------- generic single/dual GEMM (used for W12 fuse) --------------
template<bool DUAL, int EPI, int EM>
__global__ void __launch_bounds__(256, 2) tgemm(
        const __nv_bfloat16* __restrict__ Ah0, const __nv_bfloat16* __restrict__ Al0,
        const __nv_bfloat16* __restrict__ Ah1, const __nv_bfloat16* __restrict__ Al1,
        const uint32_t* __restrict__ F0, const uint32_t* __restrict__ F1,
        const float* __restrict__ bias, const float* __restrict__ addsrc,
        float* __restrict__ Cf, __nv_bfloat16* __restrict__ Ch, __nv_bfloat16* __restrict__ Cl,
        int M, int K) {
    extern __shared__ __align__(16) char dsm[];
    uint32_t base = smem_u32(dsm);

    int tid = threadIdx.x, lane = tid & 31, warp = tid >> 5;
    int warp_m = warp & 3, warp_n = warp >> 2;
    int brow = blockIdx.x * 128;

    int lr = lane & 7;
    int a_off = ((warp_m * 32 + ((lane >> 3) & 1) * 8 + lr) * TG_STRIDE + (lane >> 4) * 8) * 2;

    float acc[2][8][4];
#pragma unroll
    for (int mi = 0; mi < 2; mi++)
#pragma unroll
        for (int ni = 0; ni < 8; ni++)
#pragma unroll
            for (int c = 0; c < 4; c++) acc[mi][ni][c] = 0.0f;

    int r = tid >> 1, half = tid & 1;
    int grow = brow + r;
    bool rowok = grow < M;
    int growc = rowok ? grow : (M - 1);
    int asz = rowok ? 16 : 0;
    uint32_t s_a = r * (TG_STRIDE * 2) + half * 32;

    pipeline_gemm(base, s_a, growc, asz, K, Ah0, Al0, Ah1, Al1, F0, F1,
                  DUAL ? 2 : 1, warp_n, lane, a_off, acc);

    int g = lane >> 2, tg = lane & 3;
#pragma unroll
    for (int mi = 0; mi < 2; mi++) {
#pragma unroll
        for (int h = 0; h < 2; h++) {
            int row = brow + warp_m * 32 + mi * 16 + h * 8 + g;
            if (row >= M) continue;
#pragma unroll
            for (int ni = 0; ni < 8; ni++) {
                int col = warp_n * 64 + ni * 8 + tg * 2;
                float v0 = acc[mi][ni][h * 2 + 0] + __ldg(&bias[col]);
                float v1 = acc[mi][ni][h * 2 + 1] + __ldg(&bias[col + 1]);
                if (EPI >= 1) {
                    v0 = v0 > 0.0f ? v0 : NEG_SLOPE * v0;
                    v1 = v1 > 0.0f ? v1 : NEG_SLOPE * v1;
                }
                if (EPI == 2) {
                    float2 o = *(const float2*)(addsrc + (size_t)row * 128 + col);
                    v0 += o.x; v1 += o.y;
                }
                if (EM != 2)
                    *(float2*)(Cf + (size_t)row * 128 + col) = make_float2(v0, v1);
                if (EM >= 1) {
                    uint32_t hh, ll;
                    split2(v0, v1, hh, ll);
                    *(uint32_t*)(Ch + (size_t)row * 128 + col) = hh;
                    *(uint32_t*)(Cl + (size_t)row * 128 + col) = ll;
                }
            }
        }
    }
}

// ---------------- fused per-cell kernel: sage GEMM -> stash; cheb dual GEMM + add ----
#define CG_STASH_OFF 40960
#define CG_STRIDE 136          // floats per stash row (conflict-free)
#define CG_SMEM (40960 + 128 * CG_STRIDE * 4)   // 40960 + 69632 = 110592

template<int EM>   // 0: fp32 out only; 2: planes out only
__global__ void __launch_bounds__(256, 2) cell_gemm(
        const __nv_bfloat16* __restrict__ S_h, const __nv_bfloat16* __restrict__ S_l,
        const uint32_t* __restrict__ Fsw, const float* __restrict__ sb,
        const __nv_bfloat16* __restrict__ Xh, const __nv_bfloat16* __restrict__ Xl,
        const __nv_bfloat16* __restrict__ Th, const __nv_bfloat16* __restrict__ Tl,
        const uint32_t* __restrict__ Fc0, const uint32_t* __restrict__ Fc1,
        const float* __restrict__ cb,
        float* __restrict__ Cf, __nv_bfloat16* __restrict__ Ch, __nv_bfloat16* __restrict__ Cl,
        int M) {
    extern __shared__ __align__(16) char dsm[];
    uint32_t base = smem_u32(dsm);
    float* stash = (float*)(dsm + CG_STASH_OFF);

    int tid = threadIdx.x, lane = tid & 31, warp = tid >> 5;
    int warp_m = warp & 3, warp_n = warp >> 2;
    int brow = blockIdx.x * 128;

    int lr = lane & 7;
    int a_off = ((warp_m * 32 + ((lane >> 3) & 1) * 8 + lr) * TG_STRIDE + (lane >> 4) * 8) * 2;

    int r = tid >> 1, half = tid & 1;
    int grow = brow + r;
    bool rowok = grow < M;
    int growc = rowok ? grow : (M - 1);
    int asz = rowok ? 16 : 0;
    uint32_t s_a = r * (TG_STRIDE * 2) + half * 32;
    int g = lane >> 2, tg = lane & 3;

    float acc[2][8][4];

    // ---- phase 1: sage GEMM -> LReLU -> stash ----
#pragma unroll
    for (int mi = 0; mi < 2; mi++)
#pragma unroll
        for (int ni = 0; ni < 8; ni++)
#pragma unroll
            for (int c = 0; c < 4; c++) acc[mi][ni][c] = 0.0f;

    pipeline_gemm(base, s_a, growc, asz, 128, S_h, S_l, nullptr, nullptr,
                  Fsw, nullptr, 1, warp_n, lane, a_off, acc);

#pragma unroll
    for (int mi = 0; mi < 2; mi++) {
#pragma unroll
        for (int h = 0; h < 2; h++) {
            int rl = warp_m * 32 + mi * 16 + h * 8 + g;   // CTA-local row
#pragma unroll
            for (int ni = 0; ni < 8; ni++) {
                int col = warp_n * 64 + ni * 8 + tg * 2;
                float v0 = acc[mi][ni][h * 2 + 0] + __ldg(&sb[col]);
                float v1 = acc[mi][ni][h * 2 + 1] + __ldg(&sb[col + 1]);
                v0 = v0 > 0.0f ? v0 : NEG_SLOPE * v0;
                v1 = v1 > 0.0f ? v1 : NEG_SLOPE * v1;
                *(float2*)(stash + rl * CG_STRIDE + col) = make_float2(v0, v1);
            }
        }
    }

    // staging buffers reused by phase 2 -> all phase-1 MMAs must be done first
    __syncthreads();

    // ---- phase 2: cheb dual GEMM -> LReLU -> + stash -> out ----
#pragma unroll
    for (int mi = 0; mi < 2; mi++)
#pragma unroll
        for (int ni = 0; ni < 8; ni++)
#pragma unroll
            for (int c = 0; c < 4; c++) acc[mi][ni][c] = 0.0f;

    pipeline_gemm(base, s_a, growc, asz, 128, Xh, Xl, Th, Tl,
                  Fc0, Fc1, 2, warp_n, lane, a_off, acc);

#pragma unroll
    for (int mi = 0; mi < 2; mi++) {
#pragma unroll
        for (int h = 0; h < 2; h++) {
            int rl = warp_m * 32 + mi * 16 + h * 8 + g;
            int row = brow + rl;
            if (row >= M) continue;
#pragma unroll
            for (int ni = 0; ni < 8; ni++) {
                int col = warp_n * 64 + ni * 8 + tg * 2;
                float v0 = acc[mi][ni][h * 2 + 0] + __ldg(&cb[col]);
                float v1 = acc[mi][ni][h * 2 + 1] + __ldg(&cb[col + 1]);
                v0 = v0 > 0.0f ? v0 : NEG_SLOPE * v0;
                v1 = v1 > 0.0f ? v1 : NEG_SLOPE * v1;
                float2 o = *(const float2*)(stash + rl * CG_STRIDE + col);
                v0 += o.x; v1 += o.y;
                if (EM != 2)
                    *(float2*)(Cf + (size_t)row * 128 + col) = make_float2(v0, v1);
                if (EM >= 1) {
                    uint32_t hh, ll;
                    split2(v0, v1, hh, ll);
                    *(uint32_t*)(Ch + (size_t)row * 128 + col) = hh;
                    *(uint32_t*)(Cl + (size_t)row * 128 + col) = ll;
                }
            }
        }
    }
}

// ---------------- conv GEMM: fp32 A -> split in-kernel, double-buffered planes ----
#define CV_AF(s) ((s) * 16384)
#define CV_AH(s) (32768 + (s) * 10240)
#define CV_AL(s) (53248 + (s) * 10240)
#define CV_SMEM 73728

__global__ void __launch_bounds__(256, 2) tgemm_conv(
        const float* __restrict__ Af, const uint32_t* __restrict__ F0,
        const float* __restrict__ bias,
        float* __restrict__ Cf, __nv_bfloat16* __restrict__ Ch, __nv_bfloat16* __restrict__ Cl,
        int M, int K) {
    extern __shared__ __align__(16) char dsm[];
    uint32_t base = smem_u32(dsm);

    int tid = threadIdx.x, lane = tid & 31, warp = tid >> 5;
    int warp_m = warp & 3, warp_n = warp >> 2;
    int brow = blockIdx.x * 128;
    int K64 = K * 64;
    const uint4* F4h = (const uint4*)F0;
    const uint4* F4l = (const uint4*)(F0 + K64);

    int lr = lane & 7;
    int a_off = ((warp_m * 32 + ((lane >> 3) & 1) * 8 + lr) * TG_STRIDE + (lane >> 4) * 8) * 2;

    float acc[2][8][4];
#pragma unroll
    for (int mi = 0; mi < 2; mi++)
#pragma unroll
        for (int ni = 0; ni < 8; ni++)
#pragma unroll
            for (int c = 0; c < 4; c++) acc[mi][ni][c] = 0.0f;

    int r = tid >> 1, half = tid & 1;
    int grow = brow + r;
    bool rowok = grow < M;
    int growc = rowok ? grow : (M - 1);
    int asz = rowok ? 16 : 0;
    uint32_t s_b = r * (TG_STRIDE * 2) + half * 32;
    uint32_t s_f = r * 128 + half * 64;
    int nk = K >> 5;

    auto issue = [&](int c, int stage) {
        int k0 = c << 5;
        const char* ga = (const char*)(Af + (size_t)growc * K + k0 + half * 16);
        uint32_t af = base + CV_AF(stage) + s_f;
        cp16(af,      ga,      asz);
        cp16(af + 16, ga + 16, asz);
        cp16(af + 32, ga + 32, asz);
        cp16(af + 48, ga + 48, asz);
        asm volatile("cp.async.commit_group;");
    };

    issue(0, 0);
    for (int c = 0; c < nk; c++) {
        int cur = c & 1;
        cp_wait<0>();
        {
            const float4* ap = (const float4*)(dsm + CV_AF(cur) + s_f);
            float4 f0 = ap[0], f1 = ap[1], f2 = ap[2], f3 = ap[3];
            uint32_t h[8], l[8];
            split2(f0.x, f0.y, h[0], l[0]); split2(f0.z, f0.w, h[1], l[1]);
            split2(f1.x, f1.y, h[2], l[2]); split2(f1.z, f1.w, h[3], l[3]);
            split2(f2.x, f2.y, h[4], l[4]); split2(f2.z, f2.w, h[5], l[5]);
            split2(f3.x, f3.y, h[6], l[6]); split2(f3.z, f3.w, h[7], l[7]);
            uint4* hp = (uint4*)(dsm + CV_AH(cur) + s_b);
            uint4* lp = (uint4*)(dsm + CV_AL(cur) + s_b);
            hp[0] = make_uint4(h[0], h[1], h[2], h[3]);
            hp[1] = make_uint4(h[4], h[5], h[6], h[7]);
            lp[0] = make_uint4(l[0], l[1], l[2], l[3]);
            lp[1] = make_uint4(l[4], l[5], l[6], l[7]);
        }
        if (c + 1 < nk) issue(c + 1, cur ^ 1);
        __syncthreads();

        uint32_t uAh = base + CV_AH(cur);
        uint32_t uAl = base + CV_AL(cur);
#pragma unroll
        for (int ks = 0; ks < 2; ks++) {
            int ko = ks * 32;
            int kidx = c * 2 + ks;
            int qb = (kidx * 8 + warp_n * 4) * 32 + lane;
            uint4 fh[4], fl[4];
#pragma unroll
            for (int nj = 0; nj < 4; nj++) fh[nj] = __ldg(&F4h[qb + nj * 32]);
#pragma unroll
            for (int nj = 0; nj < 4; nj++) fl[nj] = __ldg(&F4l[qb + nj * 32]);
            uint32_t afh[2][4], afl[2][4];
#pragma unroll
            for (int mi = 0; mi < 2; mi++) {
                ldm4(afh[mi], uAh + a_off + ko + mi * 16 * TG_STRIDE * 2);
                ldm4(afl[mi], uAl + a_off + ko + mi * 16 * TG_STRIDE * 2);
            }
#pragma unroll
            for (int mi = 0; mi < 2; mi++)
#pragma unroll
                for (int ni = 0; ni < 8; ni++) {
                    uint32_t b0 = (ni & 1) ? fh[ni >> 1].z : fh[ni >> 1].x;
                    uint32_t b1 = (ni & 1) ? fh[ni >> 1].w : fh[ni >> 1].y;
                    mma16816(acc[mi][ni], afh[mi], b0, b1);
                }
#pragma unroll
            for (int mi = 0; mi < 2; mi++)
#pragma unroll
                for (int ni = 0; ni < 8; ni++) {
                    uint32_t b0 = (ni & 1) ? fh[ni >> 1].z : fh[ni >> 1].x;
                    uint32_t b1 = (ni & 1) ? fh[ni >> 1].w : fh[ni >> 1].y;
                    mma16816(acc[mi][ni], afl[mi], b0, b1);
                }
#pragma unroll
            for (int mi = 0; mi < 2; mi++)
#pragma unroll
                for (int ni = 0; ni < 8; ni++) {
                    uint32_t b0 = (ni & 1) ? fl[ni >> 1].z : fl[ni >> 1].x;
                    uint32_t b1 = (ni & 1) ? fl[ni >> 1].w : fl[ni >> 1].y;
                    mma16816(acc[mi][ni], afh[mi], b0, b1);
                }
        }
    }

    int g = lane >> 2, tg = lane & 3;
#pragma unroll
    for (int mi = 0; mi < 2; mi++) {
#pragma unroll
        for (int h = 0; h < 2; h++) {
            int row = brow + warp_m * 32 + mi * 16 + h * 8 + g;
            if (row >= M) continue;
#pragma unroll
            for (int ni = 0; ni < 8; ni++) {
                int col = warp_n * 64 + ni * 8 + tg * 2;
                float v0 = acc[mi][ni][h * 2 + 0] + __ldg(&bias[col]);
                float v1 = acc[mi][ni][h * 2 + 1] + __ldg(&bias[col + 1]);
                *(float2*)(Cf + (size_t)row * 128 + col) = make_float2(v0, v1);
                uint32_t hh, ll;
                split2(v0, v1, hh, ll);
                *(uint32_t*)(Ch + (size_t)row * 128 + col) = hh;
                *(uint32_t*)(Cl + (size_t)row * 128 + col) = ll;
            }
        }
    }
}

// ---------------- classifier + log_softmax (warp per row) ----------------
__global__ void __launch_bounds__(256) cls_kernel(
        const float* __restrict__ x, const float* __restrict__ W,
        const float* __restrict__ b, float* __restrict__ out, int M) {
    __shared__ float Wt[C_OUT][128];
    __shared__ float bs[C_OUT];
    for (int i = threadIdx.x; i < 128 * C_OUT; i += 256) {
        int k = i / C_OUT, c = i % C_OUT;
        Wt[c][k] = W[i];
    }
    if (threadIdx.x < C_OUT) bs[threadIdx.x] = b[threadIdx.x];
    __syncthreads();

    int warp = threadIdx.x >> 5, lane = threadIdx.x & 31;
    int row = blockIdx.x * 8 + warp;
    if (row >= M) return;

    float xr[4];
#pragma unroll
    for (int j = 0; j < 4; j++) xr[j] = x[(size_t)row * 128 + lane + 32 * j];

    float acc[C_OUT];
#pragma unroll
    for (int c = 0; c < C_OUT; c++) {
        float a = 0.0f;
#pragma unroll
        for (int j = 0; j < 4; j++) a += xr[j] * Wt[c][lane + 32 * j];
#pragma unroll
        for (int o = 16; o > 0; o >>= 1) a += __shfl_down_sync(0xFFFFFFFFu, a, o);
        acc[c] = a;
    }
    if (lane == 0) {
        float mx = -1e30f;
#pragma unroll
        for (int c = 0; c < C_OUT; c++) { acc[c] += bs[c]; mx = fmaxf(mx, acc[c]); }
        float se = 0.0f;
#pragma unroll
        for (int c = 0; c < C_OUT; c++) se += expf(acc[c] - mx);
        float l = mx + logf(se);
#pragma unroll
        for (int c = 0; c < C_OUT; c++) out[(size_t)row * C_OUT + c] = acc[c] - l;
    }
}

// ---------------- host ----------------
static void* symaddr(const void* sym) {
    void* p = nullptr;
    cudaGetSymbolAddress(&p, sym);
    return p;
}

extern "C" void kernel_launch(void* const* d_in, const int* in_sizes, int n_in,
                              void* d_out, int out_size) {
    const float* x   = (const float*)d_in[0];
    const int*   ei  = (const int*)d_in[1];
    const float* ew  = (const float*)d_in[2];
    const float* pre_w1 = (const float*)d_in[3];  const float* pre_b1 = (const float*)d_in[4];
    const float* cw0_1  = (const float*)d_in[5];  const float* cw1_1  = (const float*)d_in[6];
    const float* cb_1   = (const float*)d_in[7];
    const float* sw_1   = (const float*)d_in[8];  const float* sb_1   = (const float*)d_in[9];
    const float* lw_1   = (const float*)d_in[10]; const float* lb_1   = (const float*)d_in[11];
    const float* pre_w2 = (const float*)d_in[12]; const float* pre_b2 = (const float*)d_in[13];
    const float* cw0_2  = (const float*)d_in[14]; const float* cw1_2  = (const float*)d_in[15];
    const float* cb_2   = (const float*)d_in[16];
    const float* sw_2   = (const float*)d_in[17]; const float* sb_2   = (const float*)d_in[18];
    const float* lw_2   = (const float*)d_in[19]; const float* lb_2   = (const float*)d_in[20];
    const float* cls_w  = (const float*)d_in[21]; const float* cls_b  = (const float*)d_in[22];
    float* out = (float*)d_out;

    int E = in_sizes[2];
    int N = in_sizes[0] / F_IN;
    const int* src = ei;
    const int* dst = ei + E;

    float* xh    = (float*)symaddr(g_xh);
    float* tbuf  = (float*)symaddr(g_t);
    float* deg   = (float*)symaddr(g_deg);
    float* dis   = (float*)symaddr(g_dis);
    float* loopw = (float*)symaddr(g_loopw);
    float* invc  = (float*)symaddr(g_invcnt);
    int*   nloop = (int*)symaddr(g_nloop);
    int*   hist  = (int*)symaddr(g_hist);
    int*   off   = (int*)symaddr(g_off);
    int*   cur   = (int*)symaddr(g_cursor);
    int*   bsum  = (int*)symaddr(g_bsum);
    int*   esrc  = (int*)symaddr(g_esrc);
    float* enorm = (float*)symaddr(g_enorm);
    float* ewe   = (float*)symaddr(g_ewe);
    float* W12   = (float*)symaddr(g_W12);
    float* b12   = (float*)symaddr(g_b12);
    float* Wc    = (float*)symaddr(g_Wc);
    float* bc    = (float*)symaddr(g_bc);

    __nv_bfloat16* xh_h = (__nv_bfloat16*)symaddr(g_xh_h);
    __nv_bfloat16* xh_l = (__nv_bfloat16*)symaddr(g_xh_l);
    __nv_bfloat16* tx_h = (__nv_bfloat16*)symaddr(g_tx_h);
    __nv_bfloat16* tx_l = (__nv_bfloat16*)symaddr(g_tx_l);
    __nv_bfloat16* s_h  = (__nv_bfloat16*)symaddr(g_s_h);
    __nv_bfloat16* s_l  = (__nv_bfloat16*)symaddr(g_s_l);
    __nv_bfloat16* t_h  = (__nv_bfloat16*)symaddr(g_t_h);
    __nv_bfloat16* t_l  = (__nv_bfloat16*)symaddr(g_t_l);

    uint32_t* Fpre1  = (uint32_t*)symaddr(g_Fpre1);
    uint32_t* Fcw0_1 = (uint32_t*)symaddr(g_Fcw0_1);
    uint32_t* Fcw1_1 = (uint32_t*)symaddr(g_Fcw1_1);
    uint32_t* Fsw1   = (uint32_t*)symaddr(g_Fsw1);
    uint32_t* FW12   = (uint32_t*)symaddr(g_FW12);
    uint32_t* Fcw0_2 = (uint32_t*)symaddr(g_Fcw0_2);
    uint32_t* Fcw1_2 = (uint32_t*)symaddr(g_Fcw1_2);
    uint32_t* Fsw2   = (uint32_t*)symaddr(g_Fsw2);

    cudaFuncSetAttribute(tgemm<false, 0, 1>, cudaFuncAttributeMaxDynamicSharedMemorySize, TG_SMEM);
    cudaFuncSetAttribute(cell_gemm<0>, cudaFuncAttributeMaxDynamicSharedMemorySize, CG_SMEM);
    cudaFuncSetAttribute(cell_gemm<2>, cudaFuncAttributeMaxDynamicSharedMemorySize, CG_SMEM);
    cudaFuncSetAttribute(tgemm_conv,   cudaFuncAttributeMaxDynamicSharedMemorySize, CV_SMEM);

    int eB = (E + 255) / 256;
    int nB = (N + 255) / 256;
    int nbScan = (N + 1023) / 1024;
    int gG = (N + 127) / 128;
    int aggB = (N * 32 + 255) / 256;

    // ---- fork: preprocessing chain on side stream ----
    cudaStream_t s2;
    cudaStreamCreateWithFlags(&s2, cudaStreamNonBlocking);
    cudaEvent_t evA, evB;
    cudaEventCreateWithFlags(&evA, cudaEventDisableTiming);
    cudaEventCreateWithFlags(&evB, cudaEventDisableTiming);
    cudaEventRecord(evA, 0);
    cudaStreamWaitEvent(s2, evA, 0);

    setup1<<<322, 256>>>(lw_1, pre_w2, lb_1, pre_b2, lw_2, cls_w, lb_2, cls_b,
                         pre_w1, W12, b12, Wc, bc, Fpre1);
    init_nodes<<<nB, 256, 0, s2>>>(loopw, deg, nloop, hist, N);
    edge_pass1<<<eB, 256, 0, s2>>>(src, dst, ew, deg, nloop, loopw, hist, E);
    // launch #4 (ncu capture slot): K=512 GEMM
    tgemm_conv<<<gG, 256, CV_SMEM>>>(x, Fpre1, pre_b1, xh, xh_h, xh_l, N, 512);
    prestage_all<<<7 * 16, 256>>>(cw0_1, cw1_1, sw_1, W12, cw0_2, cw1_2, sw_2,
                                  Fcw0_1, Fcw1_1, Fsw1, FW12, Fcw0_2, Fcw1_2, Fsw2);
    scan1<<<nbScan, 256, 0, s2>>>(hist, bsum, deg, nloop, dis, invc, N);
    scan2<<<1, 32, 0, s2>>>(bsum, nbScan, off, N);
    scan3<<<nbScan, 256, 0, s2>>>(hist, bsum, off, cur, N);
    edge_pass2<<<eB, 256, 0, s2>>>(src, dst, ew, dis, cur, esrc, enorm, ewe, E);
    cudaEventRecord(evB, s2);
    cudaStreamWaitEvent(0, evB, 0);

    // ---- cell 1: aggregate + fused sage/cheb ----
    aggregate<<<aggB, 256>>>(xh, off, esrc, enorm, ewe, loopw, invc,
                             tx_h, tx_l, s_h, s_l, N);
    cell_gemm<2><<<gG, 256, CG_SMEM>>>(s_h, s_l, Fsw1, sb_1,
                                       xh_h, xh_l, tx_h, tx_l, Fcw0_1, Fcw1_1, cb_1,
                                       nullptr, t_h, t_l, N);

    // ---- fused lin1+pre2 ----
    tgemm<false, 0, 1><<<gG, 256, TG_SMEM>>>(t_h, t_l, nullptr, nullptr, FW12, nullptr,
                                             b12, nullptr, xh, xh_h, xh_l, N, 128);

    // ---- cell 2: aggregate + fused sage/cheb ----
    aggregate<<<aggB, 256>>>(xh, off, esrc, enorm, ewe, loopw, invc,
                             tx_h, tx_l, s_h, s_l, N);
    cell_gemm<0><<<gG, 256, CG_SMEM>>>(s_h, s_l, Fsw2, sb_2,
                                       xh_h, xh_l, tx_h, tx_l, Fcw0_2, Fcw1_2, cb_2,
                                       tbuf, nullptr, nullptr, N);

    // ---- fused lin2 + classifier + log_softmax ----
    cls_kernel<<<(N + 7) / 8, 256>>>(tbuf, Wc, bc, out, N);
}

// round 17
// speedup vs baseline: 1.0501x; 1.0501x over previous
#include <cuda_runtime.h>
#include <cuda_bf16.h>
#include <math.h>
#include <stdint.h>

// ---------------- problem constants ----------------
#define N_MAX 40000
#define E_MAX 640000
#define F_IN  512
#define H     128
#define C_OUT 40
#define NEG_SLOPE 0.01f

// ---------------- scratch (device globals; no runtime alloc) ----------------
__device__ float g_xh [N_MAX * H];
__device__ float g_t  [N_MAX * H];

__device__ __nv_bfloat16 g_xh_h[N_MAX * H];
__device__ __nv_bfloat16 g_xh_l[N_MAX * H];
__device__ __nv_bfloat16 g_tx_h[N_MAX * H];
__device__ __nv_bfloat16 g_tx_l[N_MAX * H];
__device__ __nv_bfloat16 g_s_h [N_MAX * H];
__device__ __nv_bfloat16 g_s_l [N_MAX * H];

__device__ float g_deg   [N_MAX];
__device__ float g_dis   [N_MAX];
__device__ float g_loopw [N_MAX];
__device__ float g_invcnt[N_MAX];
__device__ int   g_nloop [N_MAX];
__device__ int   g_hist  [N_MAX];
__device__ int   g_off   [N_MAX + 1];
__device__ int   g_cursor[N_MAX];
__device__ int   g_bsum  [64];
__device__ int   g_esrc  [E_MAX];
__device__ float g_enorm [E_MAX];
__device__ float g_ewe   [E_MAX];

__device__ float g_W12[H * H];
__device__ float g_b12[H];
__device__ float g_Wc [H * C_OUT];
__device__ float g_bc [C_OUT];

// B in mma-fragment order: hi plane [K*64 u32] then lo plane [K*64 u32].
__device__ uint32_t g_Fpre1 [2 * 512 * 64];
__device__ uint32_t g_Fcw0_1[2 * 128 * 64];
__device__ uint32_t g_Fcw1_1[2 * 128 * 64];
__device__ uint32_t g_Fsw1  [2 * 128 * 64];
__device__ uint32_t g_FW12  [2 * 128 * 64];
__device__ uint32_t g_Fcw0_2[2 * 128 * 64];
__device__ uint32_t g_Fcw1_2[2 * 128 * 64];
__device__ uint32_t g_Fsw2  [2 * 128 * 64];

// ---------------- helpers ----------------
__device__ __forceinline__ uint32_t smem_u32(const void* p) {
    uint32_t a;
    asm("{ .reg .u64 t; cvta.to.shared.u64 t, %1; cvt.u32.u64 %0, t; }"
        : "=r"(a) : "l"(p));
    return a;
}
__device__ __forceinline__ void split2(float a, float b, uint32_t& h, uint32_t& l) {
    asm("cvt.rn.bf16x2.f32 %0,%1,%2;" : "=r"(h) : "f"(b), "f"(a));
    float fa = __uint_as_float(h << 16);
    float fb = __uint_as_float(h & 0xFFFF0000u);
    float la = a - fa, lb = b - fb;
    asm("cvt.rn.bf16x2.f32 %0,%1,%2;" : "=r"(l) : "f"(lb), "f"(la));
}
__device__ __forceinline__ void ldm4(uint32_t* r, uint32_t addr) {
    asm volatile("ldmatrix.sync.aligned.m8n8.x4.shared.b16 {%0,%1,%2,%3},[%4];"
                 : "=r"(r[0]), "=r"(r[1]), "=r"(r[2]), "=r"(r[3]) : "r"(addr));
}
__device__ __forceinline__ void mma16816(float* d, const uint32_t* a, uint32_t b0, uint32_t b1) {
    asm volatile("mma.sync.aligned.m16n8k16.row.col.f32.bf16.bf16.f32 "
                 "{%0,%1,%2,%3},{%4,%5,%6,%7},{%8,%9},{%0,%1,%2,%3};"
                 : "+f"(d[0]), "+f"(d[1]), "+f"(d[2]), "+f"(d[3])
                 : "r"(a[0]), "r"(a[1]), "r"(a[2]), "r"(a[3]), "r"(b0), "r"(b1));
}
__device__ __forceinline__ void cp16(uint32_t dst, const void* src, int szbytes) {
    asm volatile("cp.async.cg.shared.global [%0],[%1],16,%2;"
                 :: "r"(dst), "l"(src), "r"(szbytes));
}
template<int NN> __device__ __forceinline__ void cp_wait() {
    asm volatile("cp.async.wait_group %0;" :: "n"(NN));
}

// ---------------- preprocessing kernels ----------------
__global__ void init_nodes(float* loopw, float* deg, int* nloop, int* hist, int n) {
    int i = blockIdx.x * blockDim.x + threadIdx.x;
    if (i < n) { loopw[i] = 1.0f; deg[i] = 0.0f; nloop[i] = 0; hist[i] = 0; }
}

__global__ void edge_pass1(const int* __restrict__ src, const int* __restrict__ dst,
                           const float* __restrict__ w,
                           float* __restrict__ deg, int* __restrict__ nloop,
                           float* __restrict__ loopw, int* __restrict__ hist, int E) {
    int i = blockIdx.x * blockDim.x + threadIdx.x;
    if (i >= E) return;
    int s = src[i], d = dst[i];
    float wt = w[i];
    if (s == d) {
        loopw[s] = wt;
        atomicAdd(&nloop[s], 1);
    } else {
        atomicAdd(&deg[s], wt);
    }
    atomicAdd(&hist[d], 1);
}

__global__ void scan1(const int* __restrict__ hist, int* __restrict__ bsum,
                      const float* __restrict__ deg, const int* __restrict__ nloop,
                      float* __restrict__ dis, float* __restrict__ invcnt, int n) {
    __shared__ int sh[256];
    int base = blockIdx.x * 1024;
    int s = 0;
#pragma unroll
    for (int j = 0; j < 4; j++) {
        int i = base + threadIdx.x + j * 256;
        if (i < n) {
            int h = hist[i];
            s += h;
            float dg = deg[i];
            dis[i]    = (dg > 0.0f) ? rsqrtf(dg) : 0.0f;
            invcnt[i] = 1.0f / ((float)(h - nloop[i]) + 1.0f);
        }
    }
    sh[threadIdx.x] = s;
    __syncthreads();
    for (int o = 128; o > 0; o >>= 1) {
        if (threadIdx.x < o) sh[threadIdx.x] += sh[threadIdx.x + o];
        __syncthreads();
    }
    if (threadIdx.x == 0) bsum[blockIdx.x] = sh[0];
}
__global__ void scan2(int* __restrict__ bsum, int nb, int* __restrict__ off, int n) {
    if (threadIdx.x == 0) {
        int run = 0;
        for (int i = 0; i < nb; i++) { int v = bsum[i]; bsum[i] = run; run += v; }
        off[n] = run;
    }
}
__global__ void scan3(const int* __restrict__ hist, const int* __restrict__ bsum,
                      int* __restrict__ off, int* __restrict__ cursor, int n) {
    __shared__ int sh[256];
    int base = blockIdx.x * 1024 + threadIdx.x * 4;
    int v[4]; int s = 0;
#pragma unroll
    for (int j = 0; j < 4; j++) {
        int i = base + j;
        v[j] = (i < n) ? hist[i] : 0;
        s += v[j];
    }
    sh[threadIdx.x] = s;
    __syncthreads();
    for (int o = 1; o < 256; o <<= 1) {
        int t = (threadIdx.x >= o) ? sh[threadIdx.x - o] : 0;
        __syncthreads();
        sh[threadIdx.x] += t;
        __syncthreads();
    }
    int run = bsum[blockIdx.x] + sh[threadIdx.x] - s;
#pragma unroll
    for (int j = 0; j < 4; j++) {
        int i = base + j;
        if (i < n) { off[i] = run; cursor[i] = run; }
        run += v[j];
    }
}

__global__ void edge_pass2(const int* __restrict__ src, const int* __restrict__ dst,
                           const float* __restrict__ w, const float* __restrict__ dis,
                           int* __restrict__ cursor,
                           int* __restrict__ esrc, float* __restrict__ enorm,
                           float* __restrict__ ewe, int E) {
    int i = blockIdx.x * blockDim.x + threadIdx.x;
    if (i >= E) return;
    int s = src[i], d = dst[i];
    float wt = w[i];
    float wc = (s == d) ? 0.0f : wt;
    float nm = -dis[s] * wc * dis[d];
    int pos = atomicAdd(&cursor[d], 1);
    esrc[pos]  = s;
    enorm[pos] = nm;
    ewe[pos]   = wc;
}

// warp-per-node CSR aggregation with fused sage-mean; emits bf16 hi/lo planes
__global__ void __launch_bounds__(256) aggregate(
        const float* __restrict__ xh, const int* __restrict__ off,
        const int* __restrict__ esrc, const float* __restrict__ enorm,
        const float* __restrict__ ewe,
        const float* __restrict__ loopw, const float* __restrict__ invcnt,
        __nv_bfloat16* __restrict__ txh, __nv_bfloat16* __restrict__ txl,
        __nv_bfloat16* __restrict__ sh,  __nv_bfloat16* __restrict__ sl, int N) {
    int warp = (blockIdx.x * blockDim.x + threadIdx.x) >> 5;
    int lane = threadIdx.x & 31;
    if (warp >= N) return;
    int beg = off[warp], end = off[warp + 1];
    const float4* xh4 = (const float4*)xh;
    float4 a1 = make_float4(0, 0, 0, 0);
    float4 a2 = make_float4(0, 0, 0, 0);
    int j = beg;
    for (; j + 4 <= end; j += 4) {
        int   s0 = __ldg(&esrc[j]),     s1 = __ldg(&esrc[j + 1]);
        int   s2 = __ldg(&esrc[j + 2]), s3 = __ldg(&esrc[j + 3]);
        float n0 = __ldg(&enorm[j]),     n1 = __ldg(&enorm[j + 1]);
        float n2 = __ldg(&enorm[j + 2]), n3 = __ldg(&enorm[j + 3]);
        float w0 = __ldg(&ewe[j]),       w1 = __ldg(&ewe[j + 1]);
        float w2 = __ldg(&ewe[j + 2]),   w3 = __ldg(&ewe[j + 3]);
        float4 v0 = __ldg(&xh4[(size_t)s0 * 32 + lane]);
        float4 v1 = __ldg(&xh4[(size_t)s1 * 32 + lane]);
        float4 v2 = __ldg(&xh4[(size_t)s2 * 32 + lane]);
        float4 v3 = __ldg(&xh4[(size_t)s3 * 32 + lane]);
        a1.x += n0 * v0.x + n1 * v1.x + n2 * v2.x + n3 * v3.x;
        a1.y += n0 * v0.y + n1 * v1.y + n2 * v2.y + n3 * v3.y;
        a1.z += n0 * v0.z + n1 * v1.z + n2 * v2.z + n3 * v3.z;
        a1.w += n0 * v0.w + n1 * v1.w + n2 * v2.w + n3 * v3.w;
        a2.x += w0 * v0.x + w1 * v1.x + w2 * v2.x + w3 * v3.x;
        a2.y += w0 * v0.y + w1 * v1.y + w2 * v2.y + w3 * v3.y;
        a2.z += w0 * v0.z + w1 * v1.z + w2 * v2.z + w3 * v3.z;
        a2.w += w0 * v0.w + w1 * v1.w + w2 * v2.w + w3 * v3.w;
    }
    for (; j < end; j++) {
        int sn = __ldg(&esrc[j]);
        float nm = __ldg(&enorm[j]);
        float we = __ldg(&ewe[j]);
        float4 v = __ldg(&xh4[(size_t)sn * 32 + lane]);
        a1.x += nm * v.x; a1.y += nm * v.y; a1.z += nm * v.z; a1.w += nm * v.w;
        a2.x += we * v.x; a2.y += we * v.y; a2.z += we * v.z; a2.w += we * v.w;
    }
    float lw = __ldg(&loopw[warp]);
    float ic = __ldg(&invcnt[warp]);
    float4 xv = __ldg(&xh4[(size_t)warp * 32 + lane]);
    a2.x = (a2.x + lw * xv.x) * ic;
    a2.y = (a2.y + lw * xv.y) * ic;
    a2.z = (a2.z + lw * xv.z) * ic;
    a2.w = (a2.w + lw * xv.w) * ic;
    uint32_t h0, l0, h1, l1;
    int idx = warp * 32 + lane;
    split2(a1.x, a1.y, h0, l0);
    split2(a1.z, a1.w, h1, l1);
    ((uint2*)txh)[idx] = make_uint2(h0, h1);
    ((uint2*)txl)[idx] = make_uint2(l0, l1);
    split2(a2.x, a2.y, h0, l0);
    split2(a2.z, a2.w, h1, l1);
    ((uint2*)sh)[idx] = make_uint2(h0, h1);
    ((uint2*)sl)[idx] = make_uint2(l0, l1);
}

// ---------------- setup kernels ----------------
__device__ __forceinline__ void wfuse_body(
        const float* __restrict__ A, const float* __restrict__ B,
        const float* __restrict__ bA, const float* __restrict__ bB,
        float* __restrict__ W, float* __restrict__ bOut, int K2, int blk) {
    int c = threadIdx.x;
    if (c >= K2) return;
    if (blk < H) {
        float acc = 0.0f;
        for (int j = 0; j < H; j++) acc += __ldg(&A[blk * H + j]) * __ldg(&B[j * K2 + c]);
        W[blk * K2 + c] = acc;
    } else {
        float acc = bB[c];
        for (int j = 0; j < H; j++) acc += __ldg(&bA[j]) * __ldg(&B[j * K2 + c]);
        bOut[c] = acc;
    }
}

__device__ __forceinline__ void prestage_frag(const float* __restrict__ W,
                                              uint32_t* __restrict__ out,
                                              int K, int tid, int nthreads) {
    int total = K * 64;
    for (int i = tid; i < total; i += nthreads) {
        int sub = i & 3, jo = sub >> 1, r = sub & 1;
        int q = i >> 2;
        int lane = q & 31;
        int t = q >> 5;
        int jp = t & 7, ks = t >> 3;
        int k = ks * 16 + (lane & 3) * 2 + r * 8;
        int n = (jp * 2 + jo) * 8 + (lane >> 2);
        float v0 = __ldg(&W[(size_t)k * 128 + n]);
        float v1 = __ldg(&W[(size_t)(k + 1) * 128 + n]);
        uint32_t h, l;
        split2(v0, v1, h, l);
        out[i] = h;
        out[total + i] = l;
    }
}

__global__ void setup1(
        const float* lw1, const float* pw2, const float* lb1, const float* pb2,
        const float* lw2, const float* clsw, const float* lb2, const float* clsb,
        const float* pw1,
        float* W12, float* b12, float* Wc, float* bc, uint32_t* Fpre1) {
    int b = blockIdx.x;
    if (b < 129) {
        wfuse_body(lw1, pw2, lb1, pb2, W12, b12, H, b);
    } else if (b < 258) {
        wfuse_body(lw2, clsw, lb2, clsb, Wc, bc, C_OUT, b - 129);
    } else {
        prestage_frag(pw1, Fpre1, 512, (b - 258) * 256 + threadIdx.x, 64 * 256);
    }
}

__global__ void prestage_all(
        const float* W0, const float* W1, const float* W2, const float* W3,
        const float* W4, const float* W5, const float* W6,
        uint32_t* O0, uint32_t* O1, uint32_t* O2, uint32_t* O3,
        uint32_t* O4, uint32_t* O5, uint32_t* O6) {
    int wsel = blockIdx.x >> 4;
    int bi = blockIdx.x & 15;
    const float* W; uint32_t* O;
    switch (wsel) {
        case 0: W = W0; O = O0; break;
        case 1: W = W1; O = O1; break;
        case 2: W = W2; O = O2; break;
        case 3: W = W3; O = O3; break;
        case 4: W = W4; O = O4; break;
        case 5: W = W5; O = O5; break;
        default: W = W6; O = O6; break;
    }
    prestage_frag(W, O, 128, bi * 256 + threadIdx.x, 16 * 256);
}

// ---------------- shared GEMM-pipeline core (K=128 per stream) -------------
#define TG_STRIDE 40
#define ARR_B 10240
#define STAGE_B 20480
#define TG_SMEM (2 * STAGE_B)   // 40960

__device__ __forceinline__ void pipeline_gemm(
        uint32_t base, uint32_t s_a, int growc, int asz, int K,
        const __nv_bfloat16* Ah0, const __nv_bfloat16* Al0,
        const __nv_bfloat16* Ah1, const __nv_bfloat16* Al1,
        const uint32_t* F0, const uint32_t* F1, int nstream,
        int warp_n, int lane, int a_off, float (&acc)[2][8][4]) {
    int K64 = K * 64;
    int cpa = K >> 5;
    int total = cpa * nstream;
    int tid = threadIdx.x;
    int half = tid & 1;

    auto issue2 = [&](int c, int stage) {
        int st = (c >= cpa) ? 1 : 0;
        int ci = c - (st ? cpa : 0);
        const __nv_bfloat16* Ah = st ? Ah1 : Ah0;
        const __nv_bfloat16* Al = st ? Al1 : Al0;
        int k0 = ci << 5;
        uint32_t sb = base + stage * STAGE_B + s_a;
        const char* gah = (const char*)(Ah + (size_t)growc * K + k0 + half * 16);
        const char* gal = (const char*)(Al + (size_t)growc * K + k0 + half * 16);
        cp16(sb,              gah,      asz);
        cp16(sb + 16,         gah + 16, asz);
        cp16(sb + ARR_B,      gal,      asz);
        cp16(sb + ARR_B + 16, gal + 16, asz);
        asm volatile("cp.async.commit_group;");
    };

    issue2(0, 0);
    for (int c = 0; c < total; c++) {
        int cur = c & 1;
        int st = (c >= cpa) ? 1 : 0;
        int ci = c - (st ? cpa : 0);
        const uint32_t* Fb = st ? F1 : F0;
        const uint4* F4h = (const uint4*)Fb;
        const uint4* F4l = (const uint4*)(Fb + K64);
        cp_wait<0>();
        __syncthreads();
        if (c + 1 < total) issue2(c + 1, cur ^ 1);

        uint32_t uAh = base + cur * STAGE_B;
        uint32_t uAl = uAh + ARR_B;
#pragma unroll
        for (int ks = 0; ks < 2; ks++) {
            int ko = ks * 32;
            int kidx = ci * 2 + ks;
            int qb = (kidx * 8 + warp_n * 4) * 32 + lane;
            uint4 fh[4], fl[4];
#pragma unroll
            for (int nj = 0; nj < 4; nj++) fh[nj] = __ldg(&F4h[qb + nj * 32]);
#pragma unroll
            for (int nj = 0; nj < 4; nj++) fl[nj] = __ldg(&F4l[qb + nj * 32]);
            uint32_t afh[2][4], afl[2][4];
#pragma unroll
            for (int mi = 0; mi < 2; mi++) {
                ldm4(afh[mi], uAh + a_off + ko + mi * 16 * TG_STRIDE * 2);
                ldm4(afl[mi], uAl + a_off + ko + mi * 16 * TG_STRIDE * 2);
            }
#pragma unroll
            for (int mi = 0; mi < 2; mi++)
#pragma unroll
                for (int ni = 0; ni < 8; ni++) {
                    uint32_t b0 = (ni & 1) ? fh[ni >> 1].z : fh[ni >> 1].x;
                    uint32_t b1 = (ni & 1) ? fh[ni >> 1].w : fh[ni >> 1].y;
                    mma16816(acc[mi][ni], afh[mi], b0, b1);
                }
#pragma unroll
            for (int mi = 0; mi < 2; mi++)
#pragma unroll
                for (int ni = 0; ni < 8; ni++) {
                    uint32_t b0 = (ni & 1) ? fh[ni >> 1].z : fh[ni >> 1].x;
                    uint32_t b1 = (ni & 1) ? fh[ni >> 1].w : fh[ni >> 1].y;
                    mma16816(acc[mi][ni], afl[mi], b0, b1);
                }
#pragma unroll
            for (int mi = 0; mi < 2; mi++)
#pragma unroll
                for (int ni = 0; ni < 8; ni++) {
                    uint32_t b0 = (ni & 1) ? fl[ni >> 1].z : fl[ni >> 1].x;
                    uint32_t b1 = (ni & 1) ? fl[ni >> 1].w : fl[ni >> 1].y;
                    mma16816(acc[mi][ni], afh[mi], b0, b1);
                }
        }
    }
}

// ---------------- fused per-cell kernel ----------------
// phase 1: sage GEMM -> LReLU -> stash (smem)
// phase 2: cheb dual GEMM -> LReLU -> + stash = t (kept in acc)
// P3=false: write t to Cf (fp32) and done.
// P3=true : write t as bf16 planes into stash smem, then phase 3 t@FW12+b3 ->
//           Cf (fp32) + Ch/Cl planes.
#define CG_STASH_OFF 40960
#define CG_STRIDE 136          // fp32 stash row stride (floats) / plane row stride (halves)
#define CG_PLANE_B (128 * CG_STRIDE * 2)        // 34816 bytes per bf16 plane
#define CG_SMEM (40960 + 128 * CG_STRIDE * 4)   // 110592

template<bool P3>
__global__ void __launch_bounds__(256, 2) cell_gemm(
        const __nv_bfloat16* __restrict__ S_h, const __nv_bfloat16* __restrict__ S_l,
        const uint32_t* __restrict__ Fsw, const float* __restrict__ sb,
        const __nv_bfloat16* __restrict__ Xh, const __nv_bfloat16* __restrict__ Xl,
        const __nv_bfloat16* __restrict__ Th, const __nv_bfloat16* __restrict__ Tl,
        const uint32_t* __restrict__ Fc0, const uint32_t* __restrict__ Fc1,
        const float* __restrict__ cb,
        const uint32_t* __restrict__ F3, const float* __restrict__ b3,
        float* __restrict__ Cf, __nv_bfloat16* __restrict__ Ch, __nv_bfloat16* __restrict__ Cl,
        int M) {
    extern __shared__ __align__(16) char dsm[];
    uint32_t base = smem_u32(dsm);
    float* stash = (float*)(dsm + CG_STASH_OFF);

    int tid = threadIdx.x, lane = tid & 31, warp = tid >> 5;
    int warp_m = warp & 3, warp_n = warp >> 2;
    int brow = blockIdx.x * 128;

    int lr = lane & 7;
    int a_off = ((warp_m * 32 + ((lane >> 3) & 1) * 8 + lr) * TG_STRIDE + (lane >> 4) * 8) * 2;

    int r = tid >> 1, half = tid & 1;
    int grow = brow + r;
    bool rowok = grow < M;
    int growc = rowok ? grow : (M - 1);
    int asz = rowok ? 16 : 0;
    uint32_t s_a = r * (TG_STRIDE * 2) + half * 32;
    int g = lane >> 2, tg = lane & 3;

    float acc[2][8][4];

    // ---- phase 1: sage GEMM -> LReLU -> stash ----
#pragma unroll
    for (int mi = 0; mi < 2; mi++)
#pragma unroll
        for (int ni = 0; ni < 8; ni++)
#pragma unroll
            for (int c = 0; c < 4; c++) acc[mi][ni][c] = 0.0f;

    pipeline_gemm(base, s_a, growc, asz, 128, S_h, S_l, nullptr, nullptr,
                  Fsw, nullptr, 1, warp_n, lane, a_off, acc);

#pragma unroll
    for (int mi = 0; mi < 2; mi++) {
#pragma unroll
        for (int h = 0; h < 2; h++) {
            int rl = warp_m * 32 + mi * 16 + h * 8 + g;
#pragma unroll
            for (int ni = 0; ni < 8; ni++) {
                int col = warp_n * 64 + ni * 8 + tg * 2;
                float v0 = acc[mi][ni][h * 2 + 0] + __ldg(&sb[col]);
                float v1 = acc[mi][ni][h * 2 + 1] + __ldg(&sb[col + 1]);
                v0 = v0 > 0.0f ? v0 : NEG_SLOPE * v0;
                v1 = v1 > 0.0f ? v1 : NEG_SLOPE * v1;
                *(float2*)(stash + rl * CG_STRIDE + col) = make_float2(v0, v1);
            }
        }
    }
    __syncthreads();   // phase-1 MMAs done before staging reuse; stash complete

    // ---- phase 2: cheb dual GEMM -> LReLU -> + stash = t (in acc) ----
#pragma unroll
    for (int mi = 0; mi < 2; mi++)
#pragma unroll
        for (int ni = 0; ni < 8; ni++)
#pragma unroll
            for (int c = 0; c < 4; c++) acc[mi][ni][c] = 0.0f;

    pipeline_gemm(base, s_a, growc, asz, 128, Xh, Xl, Th, Tl,
                  Fc0, Fc1, 2, warp_n, lane, a_off, acc);

#pragma unroll
    for (int mi = 0; mi < 2; mi++) {
#pragma unroll
        for (int h = 0; h < 2; h++) {
            int rl = warp_m * 32 + mi * 16 + h * 8 + g;
#pragma unroll
            for (int ni = 0; ni < 8; ni++) {
                int col = warp_n * 64 + ni * 8 + tg * 2;
                float v0 = acc[mi][ni][h * 2 + 0] + __ldg(&cb[col]);
                float v1 = acc[mi][ni][h * 2 + 1] + __ldg(&cb[col + 1]);
                v0 = v0 > 0.0f ? v0 : NEG_SLOPE * v0;
                v1 = v1 > 0.0f ? v1 : NEG_SLOPE * v1;
                float2 o = *(const float2*)(stash + rl * CG_STRIDE + col);
                acc[mi][ni][h * 2 + 0] = v0 + o.x;
                acc[mi][ni][h * 2 + 1] = v1 + o.y;
            }
        }
    }

    if (!P3) {
        // write t to global fp32 and exit
#pragma unroll
        for (int mi = 0; mi < 2; mi++) {
#pragma unroll
            for (int h = 0; h < 2; h++) {
                int row = brow + warp_m * 32 + mi * 16 + h * 8 + g;
                if (row >= M) continue;
#pragma unroll
                for (int ni = 0; ni < 8; ni++) {
                    int col = warp_n * 64 + ni * 8 + tg * 2;
                    *(float2*)(Cf + (size_t)row * 128 + col) =
                        make_float2(acc[mi][ni][h * 2 + 0], acc[mi][ni][h * 2 + 1]);
                }
            }
        }
        return;
    }

    // ---- P3: write t planes into stash smem (all reads of stash are done) ----
    __syncthreads();   // everyone finished reading stash in phase-2 epilogue
    {
        __nv_bfloat16* Tph = (__nv_bfloat16*)(dsm + CG_STASH_OFF);
        __nv_bfloat16* Tpl = (__nv_bfloat16*)(dsm + CG_STASH_OFF + CG_PLANE_B);
#pragma unroll
        for (int mi = 0; mi < 2; mi++) {
#pragma unroll
            for (int h = 0; h < 2; h++) {
                int rl = warp_m * 32 + mi * 16 + h * 8 + g;
#pragma unroll
                for (int ni = 0; ni < 8; ni++) {
                    int col = warp_n * 64 + ni * 8 + tg * 2;
                    uint32_t hh, ll;
                    split2(acc[mi][ni][h * 2 + 0], acc[mi][ni][h * 2 + 1], hh, ll);
                    *(uint32_t*)(Tph + rl * CG_STRIDE + col) = hh;
                    *(uint32_t*)(Tpl + rl * CG_STRIDE + col) = ll;
                }
            }
        }
    }
    __syncthreads();   // t planes visible

    // ---- phase 3: xh = t @ F3 + b3 (A direct from smem planes) ----
#pragma unroll
    for (int mi = 0; mi < 2; mi++)
#pragma unroll
        for (int ni = 0; ni < 8; ni++)
#pragma unroll
            for (int c = 0; c < 4; c++) acc[mi][ni][c] = 0.0f;

    {
        uint32_t uTh = base + CG_STASH_OFF;
        uint32_t uTl = uTh + CG_PLANE_B;
        int a3 = ((warp_m * 32 + ((lane >> 3) & 1) * 8 + lr) * CG_STRIDE + (lane >> 4) * 8) * 2;
        const uint4* F4h = (const uint4*)F3;
        const uint4* F4l = (const uint4*)(F3 + 128 * 64);
#pragma unroll
        for (int c = 0; c < 4; c++) {
#pragma unroll
            for (int ks = 0; ks < 2; ks++) {
                int kel = (c * 32 + ks * 16) * 2;   // byte offset within row
                int kidx = c * 2 + ks;
                int qb = (kidx * 8 + warp_n * 4) * 32 + lane;
                uint4 fh[4], fl[4];
#pragma unroll
                for (int nj = 0; nj < 4; nj++) fh[nj] = __ldg(&F4h[qb + nj * 32]);
#pragma unroll
                for (int nj = 0; nj < 4; nj++) fl[nj] = __ldg(&F4l[qb + nj * 32]);
                uint32_t afh[2][4], afl[2][4];
#pragma unroll
                for (int mi = 0; mi < 2; mi++) {
                    ldm4(afh[mi], uTh + a3 + kel + mi * 16 * CG_STRIDE * 2);
                    ldm4(afl[mi], uTl + a3 + kel + mi * 16 * CG_STRIDE * 2);
                }
#pragma unroll
                for (int mi = 0; mi < 2; mi++)
#pragma unroll
                    for (int ni = 0; ni < 8; ni++) {
                        uint32_t b0 = (ni & 1) ? fh[ni >> 1].z : fh[ni >> 1].x;
                        uint32_t b1 = (ni & 1) ? fh[ni >> 1].w : fh[ni >> 1].y;
                        mma16816(acc[mi][ni], afh[mi], b0, b1);
                    }
#pragma unroll
                for (int mi = 0; mi < 2; mi++)
#pragma unroll
                    for (int ni = 0; ni < 8; ni++) {
                        uint32_t b0 = (ni & 1) ? fh[ni >> 1].z : fh[ni >> 1].x;
                        uint32_t b1 = (ni & 1) ? fh[ni >> 1].w : fh[ni >> 1].y;
                        mma16816(acc[mi][ni], afl[mi], b0, b1);
                    }
#pragma unroll
                for (int mi = 0; mi < 2; mi++)
#pragma unroll
                    for (int ni = 0; ni < 8; ni++) {
                        uint32_t b0 = (ni & 1) ? fl[ni >> 1].z : fl[ni >> 1].x;
                        uint32_t b1 = (ni & 1) ? fl[ni >> 1].w : fl[ni >> 1].y;
                        mma16816(acc[mi][ni], afh[mi], b0, b1);
                    }
            }
        }
    }

    // epilogue: xh fp32 + split planes
#pragma unroll
    for (int mi = 0; mi < 2; mi++) {
#pragma unroll
        for (int h = 0; h < 2; h++) {
            int row = brow + warp_m * 32 + mi * 16 + h * 8 + g;
            if (row >= M) continue;
#pragma unroll
            for (int ni = 0; ni < 8; ni++) {
                int col = warp_n * 64 + ni * 8 + tg * 2;
                float v0 = acc[mi][ni][h * 2 + 0] + __ldg(&b3[col]);
                float v1 = acc[mi][ni][h * 2 + 1] + __ldg(&b3[col + 1]);
                *(float2*)(Cf + (size_t)row * 128 + col) = make_float2(v0, v1);
                uint32_t hh, ll;
                split2(v0, v1, hh, ll);
                *(uint32_t*)(Ch + (size_t)row * 128 + col) = hh;
                *(uint32_t*)(Cl + (size_t)row * 128 + col) = ll;
            }
        }
    }
}

// ---------------- conv GEMM: fp32 A -> split in-kernel, double-buffered planes ----
#define CV_AF(s) ((s) * 16384)
#define CV_AH(s) (32768 + (s) * 10240)
#define CV_AL(s) (53248 + (s) * 10240)
#define CV_SMEM 73728

__global__ void __launch_bounds__(256, 2) tgemm_conv(
        const float* __restrict__ Af, const uint32_t* __restrict__ F0,
        const float* __restrict__ bias,
        float* __restrict__ Cf, __nv_bfloat16* __restrict__ Ch, __nv_bfloat16* __restrict__ Cl,
        int M, int K) {
    extern __shared__ __align__(16) char dsm[];
    uint32_t base = smem_u32(dsm);

    int tid = threadIdx.x, lane = tid & 31, warp = tid >> 5;
    int warp_m = warp & 3, warp_n = warp >> 2;
    int brow = blockIdx.x * 128;
    int K64 = K * 64;
    const uint4* F4h = (const uint4*)F0;
    const uint4* F4l = (const uint4*)(F0 + K64);

    int lr = lane & 7;
    int a_off = ((warp_m * 32 + ((lane >> 3) & 1) * 8 + lr) * TG_STRIDE + (lane >> 4) * 8) * 2;

    float acc[2][8][4];
#pragma unroll
    for (int mi = 0; mi < 2; mi++)
#pragma unroll
        for (int ni = 0; ni < 8; ni++)
#pragma unroll
            for (int c = 0; c < 4; c++) acc[mi][ni][c] = 0.0f;

    int r = tid >> 1, half = tid & 1;
    int grow = brow + r;
    bool rowok = grow < M;
    int growc = rowok ? grow : (M - 1);
    int asz = rowok ? 16 : 0;
    uint32_t s_b = r * (TG_STRIDE * 2) + half * 32;
    uint32_t s_f = r * 128 + half * 64;
    int nk = K >> 5;

    auto issue = [&](int c, int stage) {
        int k0 = c << 5;
        const char* ga = (const char*)(Af + (size_t)growc * K + k0 + half * 16);
        uint32_t af = base + CV_AF(stage) + s_f;
        cp16(af,      ga,      asz);
        cp16(af + 16, ga + 16, asz);
        cp16(af + 32, ga + 32, asz);
        cp16(af + 48, ga + 48, asz);
        asm volatile("cp.async.commit_group;");
    };

    issue(0, 0);
    for (int c = 0; c < nk; c++) {
        int cur = c & 1;
        cp_wait<0>();
        {
            const float4* ap = (const float4*)(dsm + CV_AF(cur) + s_f);
            float4 f0 = ap[0], f1 = ap[1], f2 = ap[2], f3 = ap[3];
            uint32_t h[8], l[8];
            split2(f0.x, f0.y, h[0], l[0]); split2(f0.z, f0.w, h[1], l[1]);
            split2(f1.x, f1.y, h[2], l[2]); split2(f1.z, f1.w, h[3], l[3]);
            split2(f2.x, f2.y, h[4], l[4]); split2(f2.z, f2.w, h[5], l[5]);
            split2(f3.x, f3.y, h[6], l[6]); split2(f3.z, f3.w, h[7], l[7]);
            uint4* hp = (uint4*)(dsm + CV_AH(cur) + s_b);
            uint4* lp = (uint4*)(dsm + CV_AL(cur) + s_b);
            hp[0] = make_uint4(h[0], h[1], h[2], h[3]);
            hp[1] = make_uint4(h[4], h[5], h[6], h[7]);
            lp[0] = make_uint4(l[0], l[1], l[2], l[3]);
            lp[1] = make_uint4(l[4], l[5], l[6], l[7]);
        }
        if (c + 1 < nk) issue(c + 1, cur ^ 1);
        __syncthreads();

        uint32_t uAh = base + CV_AH(cur);
        uint32_t uAl = base + CV_AL(cur);
#pragma unroll
        for (int ks = 0; ks < 2; ks++) {
            int ko = ks * 32;
            int kidx = c * 2 + ks;
            int qb = (kidx * 8 + warp_n * 4) * 32 + lane;
            uint4 fh[4], fl[4];
#pragma unroll
            for (int nj = 0; nj < 4; nj++) fh[nj] = __ldg(&F4h[qb + nj * 32]);
#pragma unroll
            for (int nj = 0; nj < 4; nj++) fl[nj] = __ldg(&F4l[qb + nj * 32]);
            uint32_t afh[2][4], afl[2][4];
#pragma unroll
            for (int mi = 0; mi < 2; mi++) {
                ldm4(afh[mi], uAh + a_off + ko + mi * 16 * TG_STRIDE * 2);
                ldm4(afl[mi], uAl + a_off + ko + mi * 16 * TG_STRIDE * 2);
            }
#pragma unroll
            for (int mi = 0; mi < 2; mi++)
#pragma unroll
                for (int ni = 0; ni < 8; ni++) {
                    uint32_t b0 = (ni & 1) ? fh[ni >> 1].z : fh[ni >> 1].x;
                    uint32_t b1 = (ni & 1) ? fh[ni >> 1].w : fh[ni >> 1].y;
                    mma16816(acc[mi][ni], afh[mi], b0, b1);
                }
#pragma unroll
            for (int mi = 0; mi < 2; mi++)
#pragma unroll
                for (int ni = 0; ni < 8; ni++) {
                    uint32_t b0 = (ni & 1) ? fh[ni >> 1].z : fh[ni >> 1].x;
                    uint32_t b1 = (ni & 1) ? fh[ni >> 1].w : fh[ni >> 1].y;
                    mma16816(acc[mi][ni], afl[mi], b0, b1);
                }
#pragma unroll
            for (int mi = 0; mi < 2; mi++)
#pragma unroll
                for (int ni = 0; ni < 8; ni++) {
                    uint32_t b0 = (ni & 1) ? fl[ni >> 1].z : fl[ni >> 1].x;
                    uint32_t b1 = (ni & 1) ? fl[ni >> 1].w : fl[ni >> 1].y;
                    mma16816(acc[mi][ni], afh[mi], b0, b1);
                }
        }
    }

    int g = lane >> 2, tg = lane & 3;
#pragma unroll
    for (int mi = 0; mi < 2; mi++) {
#pragma unroll
        for (int h = 0; h < 2; h++) {
            int row = brow + warp_m * 32 + mi * 16 + h * 8 + g;
            if (row >= M) continue;
#pragma unroll
            for (int ni = 0; ni < 8; ni++) {
                int col = warp_n * 64 + ni * 8 + tg * 2;
                float v0 = acc[mi][ni][h * 2 + 0] + __ldg(&bias[col]);
                float v1 = acc[mi][ni][h * 2 + 1] + __ldg(&bias[col + 1]);
                *(float2*)(Cf + (size_t)row * 128 + col) = make_float2(v0, v1);
                uint32_t hh, ll;
                split2(v0, v1, hh, ll);
                *(uint32_t*)(Ch + (size_t)row * 128 + col) = hh;
                *(uint32_t*)(Cl + (size_t)row * 128 + col) = ll;
            }
        }
    }
}

// ---------------- classifier + log_softmax (warp per row) ----------------
__global__ void __launch_bounds__(256) cls_kernel(
        const float* __restrict__ x, const float* __restrict__ W,
        const float* __restrict__ b, float* __restrict__ out, int M) {
    __shared__ float Wt[C_OUT][128];
    __shared__ float bs[C_OUT];
    for (int i = threadIdx.x; i < 128 * C_OUT; i += 256) {
        int k = i / C_OUT, c = i % C_OUT;
        Wt[c][k] = W[i];
    }
    if (threadIdx.x < C_OUT) bs[threadIdx.x] = b[threadIdx.x];
    __syncthreads();

    int warp = threadIdx.x >> 5, lane = threadIdx.x & 31;
    int row = blockIdx.x * 8 + warp;
    if (row >= M) return;

    float xr[4];
#pragma unroll
    for (int j = 0; j < 4; j++) xr[j] = x[(size_t)row * 128 + lane + 32 * j];

    float acc[C_OUT];
#pragma unroll
    for (int c = 0; c < C_OUT; c++) {
        float a = 0.0f;
#pragma unroll
        for (int j = 0; j < 4; j++) a += xr[j] * Wt[c][lane + 32 * j];
#pragma unroll
        for (int o = 16; o > 0; o >>= 1) a += __shfl_down_sync(0xFFFFFFFFu, a, o);
        acc[c] = a;
    }
    if (lane == 0) {
        float mx = -1e30f;
#pragma unroll
        for (int c = 0; c < C_OUT; c++) { acc[c] += bs[c]; mx = fmaxf(mx, acc[c]); }
        float se = 0.0f;
#pragma unroll
        for (int c = 0; c < C_OUT; c++) se += expf(acc[c] - mx);
        float l = mx + logf(se);
#pragma unroll
        for (int c = 0; c < C_OUT; c++) out[(size_t)row * C_OUT + c] = acc[c] - l;
    }
}

// ---------------- host ----------------
static void* symaddr(const void* sym) {
    void* p = nullptr;
    cudaGetSymbolAddress(&p, sym);
    return p;
}

extern "C" void kernel_launch(void* const* d_in, const int* in_sizes, int n_in,
                              void* d_out, int out_size) {
    const float* x   = (const float*)d_in[0];
    const int*   ei  = (const int*)d_in[1];
    const float* ew  = (const float*)d_in[2];
    const float* pre_w1 = (const float*)d_in[3];  const float* pre_b1 = (const float*)d_in[4];
    const float* cw0_1  = (const float*)d_in[5];  const float* cw1_1  = (const float*)d_in[6];
    const float* cb_1   = (const float*)d_in[7];
    const float* sw_1   = (const float*)d_in[8];  const float* sb_1   = (const float*)d_in[9];
    const float* lw_1   = (const float*)d_in[10]; const float* lb_1   = (const float*)d_in[11];
    const float* pre_w2 = (const float*)d_in[12]; const float* pre_b2 = (const float*)d_in[13];
    const float* cw0_2  = (const float*)d_in[14]; const float* cw1_2  = (const float*)d_in[15];
    const float* cb_2   = (const float*)d_in[16];
    const float* sw_2   = (const float*)d_in[17]; const float* sb_2   = (const float*)d_in[18];
    const float* lw_2   = (const float*)d_in[19]; const float* lb_2   = (const float*)d_in[20];
    const float* cls_w  = (const float*)d_in[21]; const float* cls_b  = (const float*)d_in[22];
    float* out = (float*)d_out;

    int E = in_sizes[2];
    int N = in_sizes[0] / F_IN;
    const int* src = ei;
    const int* dst = ei + E;

    float* xh    = (float*)symaddr(g_xh);
    float* tbuf  = (float*)symaddr(g_t);
    float* deg   = (float*)symaddr(g_deg);
    float* dis   = (float*)symaddr(g_dis);
    float* loopw = (float*)symaddr(g_loopw);
    float* invc  = (float*)symaddr(g_invcnt);
    int*   nloop = (int*)symaddr(g_nloop);
    int*   hist  = (int*)symaddr(g_hist);
    int*   off   = (int*)symaddr(g_off);
    int*   cur   = (int*)symaddr(g_cursor);
    int*   bsum  = (int*)symaddr(g_bsum);
    int*   esrc  = (int*)symaddr(g_esrc);
    float* enorm = (float*)symaddr(g_enorm);
    float* ewe   = (float*)symaddr(g_ewe);
    float* W12   = (float*)symaddr(g_W12);
    float* b12   = (float*)symaddr(g_b12);
    float* Wc    = (float*)symaddr(g_Wc);
    float* bc    = (float*)symaddr(g_bc);

    __nv_bfloat16* xh_h = (__nv_bfloat16*)symaddr(g_xh_h);
    __nv_bfloat16* xh_l = (__nv_bfloat16*)symaddr(g_xh_l);
    __nv_bfloat16* tx_h = (__nv_bfloat16*)symaddr(g_tx_h);
    __nv_bfloat16* tx_l = (__nv_bfloat16*)symaddr(g_tx_l);
    __nv_bfloat16* s_h  = (__nv_bfloat16*)symaddr(g_s_h);
    __nv_bfloat16* s_l  = (__nv_bfloat16*)symaddr(g_s_l);

    uint32_t* Fpre1  = (uint32_t*)symaddr(g_Fpre1);
    uint32_t* Fcw0_1 = (uint32_t*)symaddr(g_Fcw0_1);
    uint32_t* Fcw1_1 = (uint32_t*)symaddr(g_Fcw1_1);
    uint32_t* Fsw1   = (uint32_t*)symaddr(g_Fsw1);
    uint32_t* FW12   = (uint32_t*)symaddr(g_FW12);
    uint32_t* Fcw0_2 = (uint32_t*)symaddr(g_Fcw0_2);
    uint32_t* Fcw1_2 = (uint32_t*)symaddr(g_Fcw1_2);
    uint32_t* Fsw2   = (uint32_t*)symaddr(g_Fsw2);

    cudaFuncSetAttribute(cell_gemm<true>,  cudaFuncAttributeMaxDynamicSharedMemorySize, CG_SMEM);
    cudaFuncSetAttribute(cell_gemm<false>, cudaFuncAttributeMaxDynamicSharedMemorySize, CG_SMEM);
    cudaFuncSetAttribute(tgemm_conv,       cudaFuncAttributeMaxDynamicSharedMemorySize, CV_SMEM);

    int eB = (E + 255) / 256;
    int nB = (N + 255) / 256;
    int nbScan = (N + 1023) / 1024;
    int gG = (N + 127) / 128;
    int aggB = (N * 32 + 255) / 256;

    // ---- fork: preprocessing chain on side stream ----
    cudaStream_t s2;
    cudaStreamCreateWithFlags(&s2, cudaStreamNonBlocking);
    cudaEvent_t evA, evB;
    cudaEventCreateWithFlags(&evA, cudaEventDisableTiming);
    cudaEventCreateWithFlags(&evB, cudaEventDisableTiming);
    cudaEventRecord(evA, 0);
    cudaStreamWaitEvent(s2, evA, 0);

    setup1<<<322, 256>>>(lw_1, pre_w2, lb_1, pre_b2, lw_2, cls_w, lb_2, cls_b,
                         pre_w1, W12, b12, Wc, bc, Fpre1);
    init_nodes<<<nB, 256, 0, s2>>>(loopw, deg, nloop, hist, N);
    edge_pass1<<<eB, 256, 0, s2>>>(src, dst, ew, deg, nloop, loopw, hist, E);
    // launch #4 (ncu capture slot): K=512 GEMM
    tgemm_conv<<<gG, 256, CV_SMEM>>>(x, Fpre1, pre_b1, xh, xh_h, xh_l, N, 512);
    prestage_all<<<7 * 16, 256>>>(cw0_1, cw1_1, sw_1, W12, cw0_2, cw1_2, sw_2,
                                  Fcw0_1, Fcw1_1, Fsw1, FW12, Fcw0_2, Fcw1_2, Fsw2);
    scan1<<<nbScan, 256, 0, s2>>>(hist, bsum, deg, nloop, dis, invc, N);
    scan2<<<1, 32, 0, s2>>>(bsum, nbScan, off, N);
    scan3<<<nbScan, 256, 0, s2>>>(hist, bsum, off, cur, N);
    edge_pass2<<<eB, 256, 0, s2>>>(src, dst, ew, dis, cur, esrc, enorm, ewe, E);
    cudaEventRecord(evB, s2);
    cudaStreamWaitEvent(0, evB, 0);

    // ---- cell 1 (+fused lin1+pre2 as phase 3) ----
    aggregate<<<aggB, 256>>>(xh, off, esrc, enorm, ewe, loopw, invc,
                             tx_h, tx_l, s_h, s_l, N);
    cell_gemm<true><<<gG, 256, CG_SMEM>>>(s_h, s_l, Fsw1, sb_1,
                                          xh_h, xh_l, tx_h, tx_l, Fcw0_1, Fcw1_1, cb_1,
                                          FW12, b12, xh, xh_h, xh_l, N);

    // ---- cell 2 ----
    aggregate<<<aggB, 256>>>(xh, off, esrc, enorm, ewe, loopw, invc,
                             tx_h, tx_l, s_h, s_l, N);
    cell_gemm<false><<<gG, 256, CG_SMEM>>>(s_h, s_l, Fsw2, sb_2,
                                           xh_h, xh_l, tx_h, tx_l, Fcw0_2, Fcw1_2, cb_2,
                                           nullptr, nullptr, tbuf, nullptr, nullptr, N);

    // ---- fused lin2 + classifier + log_softmax ----
    cls_kernel<<<(N + 7) / 8, 256>>>(tbuf, Wc, bc, out, N);
}